// round 2
// baseline (speedup 1.0000x reference)
#include <cuda_runtime.h>

#define B_ 64
#define T_ 1024
#define C_ 2
#define N_ 128

__global__ void __launch_bounds__(128, 1)
crf_fwd_kernel(const float* __restrict__ emissions,   // [B,T,C,N]
               const int*   __restrict__ lengths,     // [B]
               const float* __restrict__ trans,       // [1,C,N,N]
               const float* __restrict__ start_t,     // [1,C,N]
               const float* __restrict__ end_t,       // [1,C,N]
               float*       __restrict__ out)         // [B,C]
{
    const int j   = threadIdx.x;        // tag column this thread owns
    const int bc  = blockIdx.x;         // chain id
    const int b   = bc >> 1;
    const int c   = bc & 1;
    const int wid = j >> 5;
    const int len = lengths[b];

    __shared__ __align__(16) float p_sh[2][N_];
    __shared__ __align__(16) float wmax_sh[2][4];
    __shared__ __align__(16) float red_sh[4];

    // ---- Precompute E[i][j] = exp(trans[c,i,j]) for this thread's column j ----
    float e_reg[N_];
    {
        const float* tb = trans + (size_t)c * N_ * N_ + j;
#pragma unroll
        for (int k = 0; k < N_; ++k)
            e_reg[k] = __expf(tb[(size_t)k * N_]);
    }

    const float* ebase = emissions + ((size_t)b * T_ * C_ + c) * N_ + j;
    const int estride = C_ * N_;

    // ---- t = 0 init ----
    float alpha = start_t[c * N_ + j] + ebase[0];

    float w = alpha;
#pragma unroll
    for (int o = 16; o > 0; o >>= 1)
        w = fmaxf(w, __shfl_xor_sync(0xffffffffu, w, o));
    if ((j & 31) == 0) wmax_sh[0][wid] = w;
    __syncthreads();
    float4 wv0 = *reinterpret_cast<const float4*>(wmax_sh[0]);
    float m0 = fmaxf(fmaxf(wv0.x, wv0.y), fmaxf(wv0.z, wv0.w));
    p_sh[0][j] = __expf(alpha - m0);
    float m_prev = m0;   // normalizer of the p currently in p_sh[0]
    __syncthreads();

    // ---- emissions prefetch ring: slot (t & 3) holds emit for step t ----
    float ering[4];
    ering[1] = __ldg(ebase + (size_t)1 * estride);
    ering[2] = __ldg(ebase + (size_t)2 * estride);
    ering[3] = __ldg(ebase + (size_t)3 * estride);
    ering[0] = __ldg(ebase + (size_t)4 * estride);

    // ---- main scan: t = 1 .. 1024 (t = 1024 always masked since len <= T) ----
#pragma unroll 1
    for (int tb2 = 0; tb2 < 256; ++tb2) {
#pragma unroll
        for (int u = 0; u < 4; ++u) {
            const int t    = tb2 * 4 + u + 1;
            const int cur  = (u + 1) & 1;   // buffer written this step
            const int prv  = cur ^ 1;       // buffer read this step
            const int slot = (u + 1) & 3;

            // lagged max kickoff: warp maxes of alpha^{t-1} -> wmax_sh[cur]
            float wm = alpha;
#pragma unroll
            for (int o = 16; o > 0; o >>= 1)
                wm = fmaxf(wm, __shfl_xor_sync(0xffffffffu, wm, o));
            if ((j & 31) == 0) wmax_sh[cur][wid] = wm;

            // normalizer for p_t: max of alpha^{t-2} (written last step, fenced)
            float4 wv = *reinterpret_cast<const float4*>(wmax_sh[prv]);
            float m_norm = fmaxf(fmaxf(wv.x, wv.y), fmaxf(wv.z, wv.w));

            // emissions: consume + refill (4 ahead, clamped; clamped ones masked)
            float emit = ering[slot];
            int tt = t + 4;
            tt = (tt > T_ - 1) ? (T_ - 1) : tt;
            ering[slot] = __ldg(ebase + (size_t)tt * estride);

            // ---- dot: S_j = sum_i p_i * E_ij (scalar FFMA, 4 accumulators) ----
            float a0 = 0.f, a1 = 0.f, a2 = 0.f, a3 = 0.f;
            const float4* pv = reinterpret_cast<const float4*>(p_sh[prv]);
#pragma unroll
            for (int k = 0; k < 32; ++k) {
                float4 v = pv[k];
                a0 = fmaf(e_reg[4 * k + 0], v.x, a0);
                a1 = fmaf(e_reg[4 * k + 1], v.y, a1);
                a2 = fmaf(e_reg[4 * k + 2], v.z, a2);
                a3 = fmaf(e_reg[4 * k + 3], v.w, a3);
            }
            float S = (a0 + a1) + (a2 + a3);

            // alpha update (masked by ragged length), exact identity:
            // new_j = m_prev + log(S_j) + emit_j
            float anew = m_prev + emit + __logf(S);
            alpha = (t < len) ? anew : alpha;

            // normalized p for next step
            p_sh[cur][j] = __expf(alpha - m_norm);
            m_prev = m_norm;

            __syncthreads();
        }
    }

    // ---- finalize: out[b,c] = logsumexp_j(alpha_j + end[c,j]) ----
    float v = alpha + end_t[c * N_ + j];
    float wm = v;
#pragma unroll
    for (int o = 16; o > 0; o >>= 1)
        wm = fmaxf(wm, __shfl_xor_sync(0xffffffffu, wm, o));
    if ((j & 31) == 0) wmax_sh[0][wid] = wm;
    __syncthreads();
    float4 wf = *reinterpret_cast<const float4*>(wmax_sh[0]);
    float mf = fmaxf(fmaxf(wf.x, wf.y), fmaxf(wf.z, wf.w));
    float s = __expf(v - mf);
#pragma unroll
    for (int o = 16; o > 0; o >>= 1)
        s += __shfl_xor_sync(0xffffffffu, s, o);
    if ((j & 31) == 0) red_sh[wid] = s;
    __syncthreads();
    if (j == 0) {
        float Sf = (red_sh[0] + red_sh[1]) + (red_sh[2] + red_sh[3]);
        out[bc] = mf + __logf(Sf);
    }
}

extern "C" void kernel_launch(void* const* d_in, const int* in_sizes, int n_in,
                              void* d_out, int out_size) {
    // Identify inputs by element count (robust to metadata ordering).
    // emissions: 16777216, lengths: 64, transitions: 32768, start/end: 256 each.
    const float* emissions = nullptr;
    const int*   lengths   = nullptr;
    const float* trans     = nullptr;
    const float* start_t   = nullptr;
    const float* end_t     = nullptr;

    for (int i = 0; i < n_in; ++i) {
        int sz = in_sizes[i];
        if (sz == B_ * T_ * C_ * N_)      emissions = (const float*)d_in[i];
        else if (sz == B_)                lengths   = (const int*)d_in[i];
        else if (sz == C_ * N_ * N_)      trans     = (const float*)d_in[i];
    }
    // The two C_*N_ (=256) inputs: in both dict order and alphabetical order,
    // start_transitions sits at index 3; the other 256-elem input is end.
    if (n_in > 3 && in_sizes[3] == C_ * N_) start_t = (const float*)d_in[3];
    for (int i = 0; i < n_in; ++i) {
        if (in_sizes[i] == C_ * N_ && (const float*)d_in[i] != start_t) {
            end_t = (const float*)d_in[i];
        }
    }
    if (!start_t) {  // fallback: first 256-elem is start
        for (int i = 0; i < n_in; ++i)
            if (in_sizes[i] == C_ * N_) { start_t = (const float*)d_in[i]; break; }
        for (int i = 0; i < n_in; ++i)
            if (in_sizes[i] == C_ * N_ && (const float*)d_in[i] != start_t)
                end_t = (const float*)d_in[i];
    }

    float* out = (float*)d_out;
    crf_fwd_kernel<<<B_ * C_, N_>>>(emissions, lengths, trans, start_t, end_t, out);
}

// round 3
// speedup vs baseline: 1.0633x; 1.0633x over previous
#include <cuda_runtime.h>

#define B_ 64
#define T_ 1024
#define C_ 2
#define N_ 128

// ---- packed f32x2 helpers (Blackwell sm_100+) ----
__device__ __forceinline__ unsigned long long pk2(float lo, float hi) {
    unsigned long long r;
    asm("mov.b64 %0, {%1, %2};" : "=l"(r) : "f"(lo), "f"(hi));
    return r;
}
__device__ __forceinline__ void upk2(unsigned long long v, float& lo, float& hi) {
    asm("mov.b64 {%0, %1}, %2;" : "=f"(lo), "=f"(hi) : "l"(v));
}
__device__ __forceinline__ void fma2(unsigned long long& acc, unsigned long long a,
                                     unsigned long long b) {
    asm("fma.rn.f32x2 %0, %1, %2, %0;" : "+l"(acc) : "l"(a), "l"(b));
}
__device__ __forceinline__ unsigned long long add2(unsigned long long a,
                                                   unsigned long long b) {
    unsigned long long r;
    asm("add.rn.f32x2 %0, %1, %2;" : "=l"(r) : "l"(a), "l"(b));
    return r;
}

// Packed dot over ALL 128 rows: S_j = sum_i r_i * E_ij.
// rbuf must be 16B aligned. e2[m] packs rows (2m, 2m+1).
__device__ __forceinline__ float dot128(const float* rbuf,
                                        const unsigned long long* e2) {
    unsigned long long a0 = 0ull, a1 = 0ull, a2 = 0ull, a3 = 0ull;
    const ulonglong2* pv = reinterpret_cast<const ulonglong2*>(rbuf);
#pragma unroll
    for (int k = 0; k < 32; ++k) {       // 32 * 4 floats = 128 rows
        ulonglong2 v = pv[k];            // v.x = r[4k..4k+1], v.y = r[4k+2..4k+3]
        if ((k & 1) == 0) { fma2(a0, e2[2 * k], v.x); fma2(a1, e2[2 * k + 1], v.y); }
        else              { fma2(a2, e2[2 * k], v.x); fma2(a3, e2[2 * k + 1], v.y); }
    }
    a0 = add2(a0, a1);
    a2 = add2(a2, a3);
    a0 = add2(a0, a2);
    float lo, hi;
    upk2(a0, lo, hi);
    return lo + hi;
}

__global__ void __launch_bounds__(128, 1)
crf_fwd_kernel(const float* __restrict__ emissions,   // [B,T,C,N]
               const int*   __restrict__ lengths,     // [B]
               const float* __restrict__ trans,       // [1,C,N,N]
               const float* __restrict__ start_t,     // [1,C,N]
               const float* __restrict__ end_t,       // [1,C,N]
               float*       __restrict__ out)         // [B,C]
{
    const int j   = threadIdx.x;        // tag column this thread owns
    const int bc  = blockIdx.x;         // chain id
    const int b   = bc >> 1;
    const int c   = bc & 1;
    const int wid = j >> 5;
    const int len = lengths[b];         // in [T/2, T]

    __shared__ __align__(16) float r_sh[2][N_];
    __shared__ __align__(16) float red_sh[4];

    // ---- E packed: e2[m] = (exp(trans[c,2m,j]), exp(trans[c,2m+1,j])) ----
    unsigned long long e2[64];
    {
        const float* tb = trans + (size_t)c * N_ * N_ + j;
#pragma unroll
        for (int m = 0; m < 64; ++m) {
            float lo = __expf(tb[(size_t)(2 * m) * N_]);
            float hi = __expf(tb[(size_t)(2 * m + 1) * N_]);
            e2[m] = pk2(lo, hi);
        }
    }

    const float* ebase = emissions + ((size_t)b * T_ * C_ + c) * N_ + j;
    const int estride = C_ * N_;

    // ---- init: r_0 = exp(start + emit_0), unnormalized (bounded ~e^±6) ----
    r_sh[0][j] = __expf(start_t[c * N_ + j] + ebase[0]);
    float logK = 0.f;
    __syncthreads();

    // ---- emission prefetch ring (pre-exponentiated), slot (t & 3) ----
    float ering[4];
    ering[1] = __expf(__ldg(ebase + (size_t)1 * estride));
    ering[2] = __expf(__ldg(ebase + (size_t)2 * estride));
    ering[3] = __expf(__ldg(ebase + (size_t)3 * estride));
    ering[0] = __expf(__ldg(ebase + (size_t)4 * estride));

    // ---- main scan: active steps t = 1 .. len-1, early exit (uniform) ----
    int t = 1;
#pragma unroll 1
    for (; t + 3 < len; t += 4) {    // t stays ≡ 1 (mod 4)
#pragma unroll
        for (int u = 0; u < 4; ++u) {
            const int cur  = (1 + u) & 1;    // == (t+u) & 1, compile-time
            const int prv  = cur ^ 1;
            const int slot = (1 + u) & 3;    // == (t+u) & 3, compile-time
            const int tq   = t + u;

            // normalizer: previous step's tag-0 value (uniform broadcast)
            float cn  = r_sh[prv][0];
            float inv = 1.0f / cn;
            logK += __logf(cn);              // off critical path

            // emission: consume + refill 4 ahead (pre-exp'd)
            float em = ering[slot];
            int tt = tq + 4; tt = (tt > T_ - 1) ? (T_ - 1) : tt;
            ering[slot] = __expf(__ldg(ebase + (size_t)tt * estride));

            float S = dot128(r_sh[prv], e2);
            r_sh[cur][j] = S * em * inv;
            __syncthreads();
        }
    }
    // tail (≤ 3 steps)
#pragma unroll 1
    for (; t < len; ++t) {
        const int cur = t & 1;
        const int prv = cur ^ 1;
        float cn  = r_sh[prv][0];
        float inv = 1.0f / cn;
        logK += __logf(cn);
        float em = __expf(__ldg(ebase + (size_t)t * estride));
        float S = dot128(r_sh[prv], e2);
        r_sh[cur][j] = S * em * inv;
        __syncthreads();
    }

    // ---- finalize: logZ = logK + log( sum_j r_j * exp(end_j) ) ----
    float v = r_sh[(len - 1) & 1][j] * __expf(end_t[c * N_ + j]);
    float s = v;
#pragma unroll
    for (int o = 16; o > 0; o >>= 1)
        s += __shfl_xor_sync(0xffffffffu, s, o);
    if ((j & 31) == 0) red_sh[wid] = s;
    __syncthreads();
    if (j == 0) {
        float Sf = (red_sh[0] + red_sh[1]) + (red_sh[2] + red_sh[3]);
        out[bc] = logK + logf(Sf);
    }
}

extern "C" void kernel_launch(void* const* d_in, const int* in_sizes, int n_in,
                              void* d_out, int out_size) {
    // Identify inputs by element count (robust to metadata ordering).
    const float* emissions = nullptr;
    const int*   lengths   = nullptr;
    const float* trans     = nullptr;
    const float* start_t   = nullptr;
    const float* end_t     = nullptr;

    for (int i = 0; i < n_in; ++i) {
        int sz = in_sizes[i];
        if (sz == B_ * T_ * C_ * N_)      emissions = (const float*)d_in[i];
        else if (sz == B_)                lengths   = (const int*)d_in[i];
        else if (sz == C_ * N_ * N_)      trans     = (const float*)d_in[i];
    }
    if (n_in > 3 && in_sizes[3] == C_ * N_) start_t = (const float*)d_in[3];
    for (int i = 0; i < n_in; ++i) {
        if (in_sizes[i] == C_ * N_ && (const float*)d_in[i] != start_t)
            end_t = (const float*)d_in[i];
    }
    if (!start_t) {
        for (int i = 0; i < n_in; ++i)
            if (in_sizes[i] == C_ * N_) { start_t = (const float*)d_in[i]; break; }
        for (int i = 0; i < n_in; ++i)
            if (in_sizes[i] == C_ * N_ && (const float*)d_in[i] != start_t)
                end_t = (const float*)d_in[i];
    }

    float* out = (float*)d_out;
    crf_fwd_kernel<<<B_ * C_, N_>>>(emissions, lengths, trans, start_t, end_t, out);
}